// round 1
// baseline (speedup 1.0000x reference)
#include <cuda_runtime.h>

#define BATCH 16384
#define TSTEPS 60
#define HDIM 50
#define BLOCK 128
#define GRID (BATCH / BLOCK)

// Shared layout (floats):
//  w4    : 2500 float4  (10000 f)  interleaved (i,f,g,o) gate weights
//  wih4  :   50 float4  (  200 f)
//  bias4 :   50 float4  (  200 f)  b_ih + b_hh, interleaved
//  wlin  : 3000 f
//  xs    : 128*61 f  (input staging, pad to 61 for bank-conflict-free reads)
//  cs    : 128*51 f  (cell state, pad 51)
//  hn    : 128*51 f  (h_new staging, pad 51)
#define SMEM_FLOATS (10000 + 200 + 200 + 3000 + 128 * 61 + 128 * 51 + 128 * 51)

__device__ __forceinline__ float ex2f(float x) {
    float r; asm("ex2.approx.f32 %0, %1;" : "=f"(r) : "f"(x)); return r;
}
__device__ __forceinline__ float rcpf(float x) {
    float r; asm("rcp.approx.f32 %0, %1;" : "=f"(r) : "f"(x)); return r;
}
// sigmoid(x) = 1 / (1 + 2^(-x*log2e))
__device__ __forceinline__ float sigf(float x) {
    return rcpf(1.0f + ex2f(-1.4426950408889634f * x));
}
// tanh(x) = 2*sigmoid(2x) - 1
__device__ __forceinline__ float tanhf_acc(float x) {
    return fmaf(2.0f, rcpf(1.0f + ex2f(-2.8853900817779268f * x)), -1.0f);
}

__global__ void __launch_bounds__(BLOCK, 1)
lstm_fused_kernel(const float* __restrict__ x_g,
                  const float* __restrict__ wih_g,
                  const float* __restrict__ whh_g,
                  const float* __restrict__ bih_g,
                  const float* __restrict__ bhh_g,
                  const float* __restrict__ wlin_g,
                  const float* __restrict__ blin_g,
                  float* __restrict__ out_g)
{
    extern __shared__ float smem[];
    float4* w4    = (float4*)smem;                 // 2500 float4
    float4* wih4  = w4 + 2500;                     // 50
    float4* bias4 = wih4 + 50;                     // 50
    float*  wlin  = smem + 10400;                  // 3000
    float*  xs    = smem + 13400;                  // 128*61
    float*  cs    = smem + 13400 + 128 * 61;       // 128*51
    float*  hn    = cs + 128 * 51;                 // 128*51

    const int tid = threadIdx.x;

    // --- stage weights (interleave the 4 gate rows per hidden unit k) ---
    for (int idx = tid; idx < HDIM * HDIM; idx += BLOCK) {
        int k = idx / HDIM, j = idx % HDIM;
        float4 w;
        w.x = whh_g[(k        ) * HDIM + j];   // i gate
        w.y = whh_g[(k +  50  ) * HDIM + j];   // f gate
        w.z = whh_g[(k + 100  ) * HDIM + j];   // g gate
        w.w = whh_g[(k + 150  ) * HDIM + j];   // o gate
        w4[idx] = w;
    }
    if (tid < HDIM) {
        wih4[tid]  = make_float4(wih_g[tid], wih_g[tid + 50],
                                 wih_g[tid + 100], wih_g[tid + 150]);
        bias4[tid] = make_float4(bih_g[tid]       + bhh_g[tid],
                                 bih_g[tid + 50]  + bhh_g[tid + 50],
                                 bih_g[tid + 100] + bhh_g[tid + 100],
                                 bih_g[tid + 150] + bhh_g[tid + 150]);
    }
    for (int idx = tid; idx < TSTEPS * HDIM; idx += BLOCK)
        wlin[idx] = wlin_g[idx];

    // --- stage inputs: global is contiguous for this block's batch slice ---
    {
        const float* xin = x_g + (size_t)blockIdx.x * BLOCK * TSTEPS;
        for (int idx = tid; idx < BLOCK * TSTEPS; idx += BLOCK) {
            int bl = idx / TSTEPS, t = idx % TSTEPS;
            xs[bl * 61 + t] = xin[idx];
        }
    }
    for (int idx = tid; idx < BLOCK * 51; idx += BLOCK) cs[idx] = 0.0f;
    __syncthreads();

    // --- recurrence: one thread = one batch element ---
    float h[HDIM];
#pragma unroll
    for (int j = 0; j < HDIM; j++) h[j] = 0.0f;

    float acc_out = 0.0f;
    const float* myx = xs + tid * 61;
    float*       myc = cs + tid * 51;
    float*       myh = hn + tid * 51;

    for (int t = 0; t < TSTEPS; t++) {
        const float xv = myx[t];
        const float* wl = wlin + t * HDIM;

#pragma unroll 2
        for (int k = 0; k < HDIM; k++) {
            const float4 wi_ = wih4[k];
            const float4 bb  = bias4[k];
            float ai = fmaf(xv, wi_.x, bb.x);
            float af = fmaf(xv, wi_.y, bb.y);
            float ag = fmaf(xv, wi_.z, bb.z);
            float ao = fmaf(xv, wi_.w, bb.w);

            const float4* wr = w4 + k * HDIM;
#pragma unroll
            for (int j = 0; j < HDIM; j++) {
                const float4 w = wr[j];
                ai = fmaf(h[j], w.x, ai);
                af = fmaf(h[j], w.y, af);
                ag = fmaf(h[j], w.z, ag);
                ao = fmaf(h[j], w.w, ao);
            }

            const float ig = sigf(ai);
            const float fg = sigf(af);
            const float og = sigf(ao);
            const float gg = tanhf_acc(ag);

            const float cn = fmaf(fg, myc[k], ig * gg);
            myc[k] = cn;
            const float hv = og * tanhf_acc(cn);
            myh[k] = hv;
            acc_out = fmaf(hv, wl[k], acc_out);
        }

#pragma unroll
        for (int j = 0; j < HDIM; j++) h[j] = myh[j];
    }

    out_g[(size_t)blockIdx.x * BLOCK + tid] = acc_out + blin_g[0];
}

extern "C" void kernel_launch(void* const* d_in, const int* in_sizes, int n_in,
                              void* d_out, int out_size)
{
    const float* x    = (const float*)d_in[0];
    const float* wih  = (const float*)d_in[1];
    const float* whh  = (const float*)d_in[2];
    const float* bih  = (const float*)d_in[3];
    const float* bhh  = (const float*)d_in[4];
    const float* wlin = (const float*)d_in[5];
    const float* blin = (const float*)d_in[6];
    float* out = (float*)d_out;

    const size_t smem_bytes = (size_t)SMEM_FLOATS * sizeof(float);
    cudaFuncSetAttribute(lstm_fused_kernel,
                         cudaFuncAttributeMaxDynamicSharedMemorySize,
                         (int)smem_bytes);
    lstm_fused_kernel<<<GRID, BLOCK, smem_bytes>>>(x, wih, whh, bih, bhh,
                                                   wlin, blin, out);
}

// round 2
// speedup vs baseline: 1.0650x; 1.0650x over previous
#include <cuda_runtime.h>

#define BATCH  16384
#define TSTEPS 60
#define HDIM   50
#define BLOCK  256           // threads per block
#define ELPB   128           // elements per block (2 threads per element)
#define GRID   (BATCH / ELPB)

// Shared layout (floats):
//  wsh  : 2500 float4 (10000 f)  per-parity gate-pair weights, j-paired
//  wib  :  100 float4 (  400 f)  (wih_gA, wih_gB, biasA, biasB) per (par,k)
//  wlin : 3000 f
//  xs   : 128*61 f   (inputs, padded)
//  cs   : 128*51 f   (cell state per element)
//  hn   : 128*51 f   (h staging per element)
#define SMEM_FLOATS (10000 + 400 + 3000 + 128 * 61 + 128 * 51 + 128 * 51)

__device__ __forceinline__ float ex2f(float x) {
    float r; asm("ex2.approx.f32 %0, %1;" : "=f"(r) : "f"(x)); return r;
}
__device__ __forceinline__ float rcpf(float x) {
    float r; asm("rcp.approx.f32 %0, %1;" : "=f"(r) : "f"(x)); return r;
}
// packed dual-fp32 fma: d = a*b + d  (lo,hi lanes independently)
__device__ __forceinline__ void ffma2(unsigned long long& d,
                                      unsigned long long a,
                                      unsigned long long b) {
    asm("fma.rn.f32x2 %0, %1, %2, %0;" : "+l"(d) : "l"(a), "l"(b));
}
__device__ __forceinline__ unsigned long long packf2(float lo, float hi) {
    unsigned long long r;
    asm("mov.b64 %0, {%1, %2};" : "=l"(r) : "f"(lo), "f"(hi));
    return r;
}
__device__ __forceinline__ void unpackf2(unsigned long long v, float& lo, float& hi) {
    asm("mov.b64 {%0, %1}, %2;" : "=f"(lo), "=f"(hi) : "l"(v));
}

__global__ void __launch_bounds__(BLOCK, 1)
lstm_pair_kernel(const float* __restrict__ x_g,
                 const float* __restrict__ wih_g,
                 const float* __restrict__ whh_g,
                 const float* __restrict__ bih_g,
                 const float* __restrict__ bhh_g,
                 const float* __restrict__ wlin_g,
                 const float* __restrict__ blin_g,
                 float* __restrict__ out_g)
{
    extern __shared__ float smem[];
    float4* wsh  = (float4*)smem;                    // 2500 float4
    float4* wib  = wsh + 2500;                       // 100 float4
    float*  wlin = smem + 10400;                     // 3000
    float*  xs   = smem + 13400;                     // 128*61
    float*  cs   = xs + ELPB * 61;                   // 128*51
    float*  hn   = cs + ELPB * 51;                   // 128*51

    const int tid = threadIdx.x;
    const int par = tid & 1;        // 0: gates (i,f)   1: gates (g,o)
    const int e   = tid >> 1;       // element within block

    // ---- stage gate weights: wsh[(par*50 + k)*25 + jp] =
    //      (gA[2jp], gA[2jp+1], gB[2jp], gB[2jp+1])
    for (int idx = tid; idx < 2500; idx += BLOCK) {
        int p = idx / 1250, rem = idx % 1250;
        int k = rem / 25,   jp  = rem % 25;
        int rA = k + (p ? 100 : 0);     // i-row or g-row
        int rB = rA + 50;               // f-row or o-row
        wsh[idx] = make_float4(whh_g[rA * HDIM + 2 * jp],
                               whh_g[rA * HDIM + 2 * jp + 1],
                               whh_g[rB * HDIM + 2 * jp],
                               whh_g[rB * HDIM + 2 * jp + 1]);
    }
    if (tid < 100) {
        int p = tid / 50, k = tid % 50;
        int gA = k + (p ? 100 : 0), gB = gA + 50;
        wib[tid] = make_float4(wih_g[gA], wih_g[gB],
                               bih_g[gA] + bhh_g[gA],
                               bih_g[gB] + bhh_g[gB]);
    }
    for (int idx = tid; idx < TSTEPS * HDIM; idx += BLOCK)
        wlin[idx] = wlin_g[idx];
    {
        const float* xin = x_g + (size_t)blockIdx.x * ELPB * TSTEPS;
        for (int idx = tid; idx < ELPB * TSTEPS; idx += BLOCK) {
            int el = idx / TSTEPS, t = idx % TSTEPS;
            xs[el * 61 + t] = xin[idx];
        }
    }
    for (int idx = tid; idx < ELPB * 51; idx += BLOCK) cs[idx] = 0.0f;
    __syncthreads();

    // ---- per-parity activation constants for act0 (sig for par0, tanh for par1)
    const float L  = 1.4426950408889634f;       // log2(e)
    const float M0 = par ? -2.0f * L : -L;
    const float S0 = par ?  2.0f     :  1.0f;
    const float B0 = par ? -1.0f     :  0.0f;

    unsigned long long hp[25];                  // packed h pairs (lo=even j)
#pragma unroll
    for (int jp = 0; jp < 25; jp++) hp[jp] = 0ull;

    float acc = 0.0f;
    const float4* myw = wsh + par * 1250;
    const float4* myb = wib + par * 50;
    float*        myc = cs + e * 51;
    float*        myh = hn + e * 51;
    const float*  myx = xs + e * 61;

    for (int t = 0; t < TSTEPS; t++) {
        const float xv = myx[t];
        const float* wl = wlin + t * HDIM;

#pragma unroll 2
        for (int k = 0; k < HDIM; k++) {
            const float4 b = myb[k];
            unsigned long long pA = 0ull, pB = 0ull;
            const ulonglong2* wr = (const ulonglong2*)(myw + k * 25);
#pragma unroll
            for (int jp = 0; jp < 25; jp++) {
                const ulonglong2 w = wr[jp];   // one LDS.128: 4 weights
                ffma2(pA, hp[jp], w.x);        // gate A partials (even,odd j)
                ffma2(pB, hp[jp], w.y);        // gate B partials
            }
            float aLo, aHi, bLo, bHi;
            unpackf2(pA, aLo, aHi);
            unpackf2(pB, bLo, bHi);
            const float s0 = fmaf(xv, b.x, b.z) + aLo + aHi;  // a_i | a_g
            const float s1 = fmaf(xv, b.y, b.w) + bLo + bHi;  // a_f | a_o

            // act0: sig(s0) on par0, tanh(s0) on par1 (shared sig core)
            const float act0 = fmaf(S0, rcpf(1.0f + ex2f(M0 * s0)), B0);
            // act1: sigmoid for both parities (f | o)
            const float act1 = rcpf(1.0f + ex2f(-L * s1));

            const float r0 = __shfl_xor_sync(0xffffffffu, act0, 1);
            const float r1 = __shfl_xor_sync(0xffffffffu, act1, 1);

            const float ig   = act0 * r0;            // sig(i)*tanh(g), both lanes
            const float fsel = par ? r1 : act1;      // sig(f)
            const float osel = par ? act1 : r1;      // sig(o)

            const float cn = fmaf(fsel, myc[k], ig);
            myc[k] = cn;                             // benign same-value collision
            const float th = fmaf(2.0f, rcpf(1.0f + ex2f(-2.0f * L * cn)), -1.0f);
            const float hv = osel * th;
            myh[k] = hv;                             // benign same-value collision
            acc = fmaf(hv, wl[k], acc);
        }

        __syncwarp();
#pragma unroll
        for (int jp = 0; jp < 25; jp++)
            hp[jp] = packf2(myh[2 * jp], myh[2 * jp + 1]);
        __syncwarp();
    }

    if (par == 0)
        out_g[(size_t)blockIdx.x * ELPB + e] = acc + blin_g[0];
}

extern "C" void kernel_launch(void* const* d_in, const int* in_sizes, int n_in,
                              void* d_out, int out_size)
{
    const float* x    = (const float*)d_in[0];
    const float* wih  = (const float*)d_in[1];
    const float* whh  = (const float*)d_in[2];
    const float* bih  = (const float*)d_in[3];
    const float* bhh  = (const float*)d_in[4];
    const float* wlin = (const float*)d_in[5];
    const float* blin = (const float*)d_in[6];
    float* out = (float*)d_out;

    const size_t smem_bytes = (size_t)SMEM_FLOATS * sizeof(float);
    cudaFuncSetAttribute(lstm_pair_kernel,
                         cudaFuncAttributeMaxDynamicSharedMemorySize,
                         (int)smem_bytes);
    lstm_pair_kernel<<<GRID, BLOCK, smem_bytes>>>(x, wih, whh, bih, bhh,
                                                  wlin, blin, out);
}